// round 9
// baseline (speedup 1.0000x reference)
#include <cuda_runtime.h>
#include <math.h>

// DifferentiableICP: B=32, N=M=2048, 5 soft-ICP iterations.
// R8: single persistent kernel for all 5 iterations. Target constants staged
//     to smem ONCE; iterations separated by per-batch device barriers
//     (arrive counter + go flag, gpu-scope fences). 1024 CTAs @ 8/SM
//     (launch_bounds(128,8), 27KB smem) -> all co-resident, barrier-safe.
// Mainloop identical to R7 (MUFU.EX2-paced, ~30.6us/iter floor); this round
// removes the ~4-5us/iter staging + launch + update-kernel overhead.

#define BB 32
#define NN 2048
#define MM 2048
#define ITERS 5
#define CHUNKS 32                    // CTAs per batch
#define ROWS_PER_CTA (NN / CHUNKS)   // 64
#define RPT 2                        // rows per thread
#define MSPLIT 4                     // warps per CTA == M segments
#define TPB (32 * MSPLIT)            // 128
#define NPAIR (MM / 2)               // 1024 packed target pairs
#define SEGPAIRS (NPAIR / MSPLIT)    // 256 pairs per segment

typedef unsigned long long ull;

// Scratch (allocation-free rule: __device__ globals)
__device__ ulonglong2 g_uv2[BB][NPAIR];        // packed ((2L2E*tx),(2L2E*ty)) pairs
__device__ ull        g_w2[BB][NPAIR];         // packed (-L2E*|t|^2) pairs
__device__ volatile float g_T[BB][4];          // (cos, sin, tx, ty)
__device__ volatile float g_part[BB][CHUNKS][8];
__device__ volatile int   g_cnt[ITERS][BB];    // per-batch arrival counters
__device__ volatile int   g_go[ITERS][BB];     // per-batch release flags

// ---- packed f32x2 helpers (PTX-only; ptxas never auto-fuses FFMA2) --------
__device__ __forceinline__ ull fma2(ull a, ull b, ull c) {
    ull d; asm("fma.rn.f32x2 %0, %1, %2, %3;" : "=l"(d) : "l"(a), "l"(b), "l"(c));
    return d;
}
__device__ __forceinline__ ull add2(ull a, ull b) {
    ull d; asm("add.rn.f32x2 %0, %1, %2;" : "=l"(d) : "l"(a), "l"(b));
    return d;
}
__device__ __forceinline__ ull pack2(float lo, float hi) {
    ull d; asm("mov.b64 %0, {%1, %2};" : "=l"(d) : "f"(lo), "f"(hi));
    return d;
}
__device__ __forceinline__ void unpack2(ull v, float& lo, float& hi) {
    asm("mov.b64 {%0, %1}, %2;" : "=f"(lo), "=f"(hi) : "l"(v));
}
__device__ __forceinline__ float ex2f(float x) {
    float e; asm("ex2.approx.ftz.f32 %0, %1;" : "=f"(e) : "f"(x));
    return e;
}

// ---------------------------------------------------------------------------
// Init: paired, log2e-folded target constants + initial transform + reset
// the barrier state (graph replays re-run this, so every replay starts clean).
// ---------------------------------------------------------------------------
__global__ void icp_init_kernel(const float* __restrict__ target,
                                const float* __restrict__ init_t) {
    int g = blockIdx.x * blockDim.x + threadIdx.x;
    if (g < BB * NPAIR) {
        int b = g >> 10, p = g & (NPAIR - 1);
        float4 f = reinterpret_cast<const float4*>(target)[(size_t)b * NPAIR + p];
        const float L2E = 1.4426950408889634f;
        ulonglong2 uv;
        uv.x = pack2(2.0f * L2E * f.x, 2.0f * L2E * f.z);
        uv.y = pack2(2.0f * L2E * f.y, 2.0f * L2E * f.w);
        g_uv2[b][p] = uv;
        g_w2[b][p]  = pack2(-L2E * (f.x * f.x + f.y * f.y),
                            -L2E * (f.z * f.z + f.w * f.w));
    }
    if (g < BB) {
        float th = init_t[g * 3 + 0];
        g_T[g][0] = cosf(th);
        g_T[g][1] = sinf(th);
        g_T[g][2] = init_t[g * 3 + 1];
        g_T[g][3] = init_t[g * 3 + 2];
    }
    if (g < ITERS * BB) {
        g_cnt[g / BB][g % BB] = 0;
        g_go[g / BB][g % BB]  = 0;
    }
}

// ---------------------------------------------------------------------------
// Persistent kernel: all 5 iterations. grid = BB*CHUNKS = 1024 CTAs, TPB=128.
// Warp w == M-segment w (uniform LDS -> broadcast). Lane l owns rows
// {l, l+32} of the CTA's 64-row chunk. 8 CTAs/SM -> full grid co-resident.
// ---------------------------------------------------------------------------
__global__ void __launch_bounds__(TPB, 8)
icp_main_kernel(const float* __restrict__ source, float* __restrict__ out) {
    __shared__ ulonglong2 sUV[NPAIR];                     // 16 KB
    __shared__ ull        sW[NPAIR];                      // 8 KB
    __shared__ float4     sRow[MSPLIT - 1][ROWS_PER_CTA]; // 3 KB

    const int b     = blockIdx.x >> 5;
    const int chunk = blockIdx.x & 31;
    const int tid   = threadIdx.x;
    const int lane  = tid & 31;
    const int warp  = tid >> 5;          // == M-segment

    // Stage paired target constants ONCE (coalesced 16B/8B loads)
    for (int i = tid; i < NPAIR; i += TPB) {
        sUV[i] = g_uv2[b][i];
        sW[i]  = g_w2[b][i];
    }

    // Raw source points for this thread's 2 rows (kept in regs all 5 iters)
    float2 sv[RPT];
    #pragma unroll
    for (int k = 0; k < RPT; ++k) {
        const int row = chunk * ROWS_PER_CTA + lane + 32 * k;
        sv[k] = reinterpret_cast<const float2*>(source)[(size_t)b * NN + row];
    }

    __syncthreads();

    for (int it = 0; it < ITERS; ++it) {
        // Current transform (volatile -> L2; updated by chunk-0 each iter)
        const float c  = g_T[b][0];
        const float s  = g_T[b][1];
        const float tx = g_T[b][2];
        const float ty = g_T[b][3];

        float sx[RPT], sy[RPT];
        ull sx2[RPT], sy2[RPT];
        #pragma unroll
        for (int k = 0; k < RPT; ++k) {
            sx[k] = c * sv[k].x - s * sv[k].y + tx;
            sy[k] = s * sv[k].x + c * sv[k].y + ty;
            sx2[k] = pack2(sx[k], sx[k]);
            sy2[k] = pack2(sy[k], sy[k]);
        }

        // Packed single-pass softmax-weighted sums: 2 LDS/pair, reused x2 rows.
        ull se2[RPT], au2[RPT], av2[RPT];
        #pragma unroll
        for (int k = 0; k < RPT; ++k) { se2[k] = 0ull; au2[k] = 0ull; av2[k] = 0ull; }

        const int p0 = warp * SEGPAIRS;
        #pragma unroll 4
        for (int p = p0; p < p0 + SEGPAIRS; ++p) {
            const ulonglong2 uv = sUV[p];
            const ull u2 = uv.x;
            const ull v2 = uv.y;
            const ull w2 = sW[p];
            #pragma unroll
            for (int k = 0; k < RPT; ++k) {
                ull y2 = fma2(sx2[k], u2, w2);
                y2 = fma2(sy2[k], v2, y2);
                float y0, y1; unpack2(y2, y0, y1);
                const ull e2 = pack2(ex2f(y0), ex2f(y1));
                se2[k] = add2(se2[k], e2);
                au2[k] = fma2(e2, u2, au2[k]);
                av2[k] = fma2(e2, v2, av2[k]);
            }
        }

        // Horizontal add of packed halves (fixed order: lo + hi)
        float se[RPT], au[RPT], av[RPT];
        #pragma unroll
        for (int k = 0; k < RPT; ++k) {
            float a0, a1;
            unpack2(se2[k], a0, a1); se[k] = a0 + a1;
            unpack2(au2[k], a0, a1); au[k] = a0 + a1;
            unpack2(av2[k], a0, a1); av[k] = a0 + a1;
        }

        // Publish segment partials (warps 1..3), combine in warp 0 (fixed order)
        if (warp > 0) {
            #pragma unroll
            for (int k = 0; k < RPT; ++k)
                sRow[warp - 1][lane + 32 * k] = make_float4(se[k], au[k], av[k], 0.0f);
        }
        __syncthreads();

        if (warp == 0) {
            float p[8];
            #pragma unroll
            for (int i = 0; i < 8; ++i) p[i] = 0.0f;

            #pragma unroll
            for (int k = 0; k < RPT; ++k) {
                float sek = se[k], auk = au[k], avk = av[k];
                #pragma unroll
                for (int q = 0; q < MSPLIT - 1; ++q) {   // fixed order seg1..3
                    const float4 f = sRow[q][lane + 32 * k];
                    sek += f.x; auk += f.y; avk += f.z;
                }
                const float KINV = 0.34657359027997264f; // ln(2)/2
                const float inv = KINV / sek;
                const float tcx = auk * inv;
                const float tcy = avk * inv;
                p[0] += sx[k];        p[1] += sy[k];
                p[2] += tcx;          p[3] += tcy;
                p[4] += sx[k] * tcx;  p[5] += sx[k] * tcy;
                p[6] += sy[k] * tcx;  p[7] += sy[k] * tcy;
            }

            #pragma unroll
            for (int off = 16; off; off >>= 1)
                #pragma unroll
                for (int i = 0; i < 8; ++i)
                    p[i] += __shfl_xor_sync(0xFFFFFFFFu, p[i], off);

            if (lane == 0) {
                #pragma unroll
                for (int i = 0; i < 8; ++i) g_part[b][chunk][i] = p[i];
                __threadfence();                       // release partials
                atomicAdd((int*)&g_cnt[it][b], 1);     // arrive
            }
        }

        // ---- chunk-0 warp-0: batch update (reduce + polar SVD + compose) ----
        if (chunk == 0 && warp == 0) {
            if (lane == 0) {
                while (g_cnt[it][b] < CHUNKS) __nanosleep(64);
            }
            __syncwarp();
            __threadfence();                           // acquire (flush L1D)

            float p[8];
            #pragma unroll
            for (int k = 0; k < 8; ++k) p[k] = g_part[b][lane][k];
            #pragma unroll
            for (int off = 16; off; off >>= 1)
                #pragma unroll
                for (int k = 0; k < 8; ++k)
                    p[k] += __shfl_xor_sync(0xFFFFFFFFu, p[k], off);

            if (lane == 0) {
                const float invN = 1.0f / (float)NN;
                const float csx = p[0] * invN, csy = p[1] * invN;
                const float ctx = p[2] * invN, cty = p[3] * invN;

                const float h00 = p[4] - p[0] * p[2] * invN;
                const float h01 = p[5] - p[0] * p[3] * invN;
                const float h10 = p[6] - p[1] * p[2] * invN;
                const float h11 = p[7] - p[1] * p[3] * invN;

                // R_delta = V @ U^T == orthogonal polar factor of H^T.
                const float E  = 0.5f * (h00 + h11);
                const float F  = 0.5f * (h00 - h11);
                const float G  = 0.5f * (h01 + h10);
                const float Hh = 0.5f * (h01 - h10);
                const float det = h00 * h11 - h01 * h10;

                float r00, r01, r10, r11;
                if (det >= 0.0f) {           // rotation branch
                    float iq = rsqrtf(E * E + Hh * Hh);
                    r00 =  E * iq;  r01 = -Hh * iq;
                    r10 = Hh * iq;  r11 =  E * iq;
                } else {                      // reflection branch
                    float ir = rsqrtf(F * F + G * G);
                    r00 =  F * ir;  r01 =  G * ir;
                    r10 =  G * ir;  r11 = -F * ir;
                }

                const float ih = rsqrtf(r00 * r00 + r10 * r10);
                const float cD = r00 * ih;
                const float sD = r10 * ih;
                const float tDx = ctx - (r00 * csx + r01 * csy);
                const float tDy = cty - (r10 * csx + r11 * csy);

                const float cc = g_T[b][0], ss = g_T[b][1];
                const float ttx = g_T[b][2], tty = g_T[b][3];
                const float c2  = cD * cc - sD * ss;
                const float s2  = sD * cc + cD * ss;
                const float tx2 = cD * ttx - sD * tty + tDx;
                const float ty2 = sD * ttx + cD * tty + tDy;
                g_T[b][0] = c2; g_T[b][1] = s2; g_T[b][2] = tx2; g_T[b][3] = ty2;

                if (it == ITERS - 1) {
                    out[b * 3 + 0] = atan2f(s2, c2);
                    out[b * 3 + 1] = tx2;
                    out[b * 3 + 2] = ty2;
                }
                __threadfence();              // release g_T (+ out)
                g_go[it][b] = 1;              // release flag
            }
        }

        // ---- all CTAs of batch b: wait for this iteration's update ----
        if (tid == 0) {
            while (!g_go[it][b]) __nanosleep(64);
        }
        __syncthreads();        // CTA-wide order after the spin
        __threadfence();        // acquire: flush L1D so next g_T read is fresh
    }
}

// ---------------------------------------------------------------------------
extern "C" void kernel_launch(void* const* d_in, const int* in_sizes, int n_in,
                              void* d_out, int out_size) {
    const float* source = (const float*)d_in[0];   // (32, 2048, 2)
    const float* target = (const float*)d_in[1];   // (32, 2048, 2)
    const float* init_t = (const float*)d_in[2];   // (32, 3)
    float* out = (float*)d_out;                    // (32, 3)

    icp_init_kernel<<<(BB * NPAIR + 255) / 256, 256>>>(target, init_t);
    icp_main_kernel<<<BB * CHUNKS, TPB>>>(source, out);
}

// round 10
// speedup vs baseline: 1.1081x; 1.1081x over previous
#include <cuda_runtime.h>
#include <math.h>

// DifferentiableICP: B=32, N=M=2048, 5 soft-ICP iterations.
// R9: revert persistent-kernel experiment (barriers cost more than launches).
//     Keep R7 structure but FOLD the per-iteration update into the head of the
//     next iter kernel: every CTA redundantly reduces g_part (8 L2 LDGs +
//     butterfly + ~50 flops, bit-identical across CTAs) and composes the new
//     transform, overlapped with smem staging. T double-buffered by iteration
//     parity so late CTAs can't see the next value. 11 launches -> 7.
// Mainloop unchanged from R7: MUFU.EX2-paced, 2 LDS/pair, f32x2 FMA.

#define BB 32
#define NN 2048
#define MM 2048
#define ITERS 5
#define CHUNKS 32                    // CTAs per batch
#define ROWS_PER_CTA (NN / CHUNKS)   // 64
#define RPT 2                        // rows per thread
#define MSPLIT 4                     // warps per CTA == M segments
#define TPB (32 * MSPLIT)            // 128
#define NPAIR (MM / 2)               // 1024 packed target pairs
#define SEGPAIRS (NPAIR / MSPLIT)    // 256 pairs per segment

typedef unsigned long long ull;

// Scratch (allocation-free rule: __device__ globals)
__device__ ulonglong2 g_uv2[BB][NPAIR]; // packed ((2L2E*tx),(2L2E*ty)) pairs
__device__ ull        g_w2[BB][NPAIR];  // packed (-L2E*|t|^2) pairs
__device__ float      g_Tbuf[2][BB][4]; // (cos,sin,tx,ty), double-buffered
__device__ float      g_part[BB][CHUNKS][8];

// ---- packed f32x2 helpers (PTX-only; ptxas never auto-fuses FFMA2) --------
__device__ __forceinline__ ull fma2(ull a, ull b, ull c) {
    ull d; asm("fma.rn.f32x2 %0, %1, %2, %3;" : "=l"(d) : "l"(a), "l"(b), "l"(c));
    return d;
}
__device__ __forceinline__ ull add2(ull a, ull b) {
    ull d; asm("add.rn.f32x2 %0, %1, %2;" : "=l"(d) : "l"(a), "l"(b));
    return d;
}
__device__ __forceinline__ ull pack2(float lo, float hi) {
    ull d; asm("mov.b64 %0, {%1, %2};" : "=l"(d) : "f"(lo), "f"(hi));
    return d;
}
__device__ __forceinline__ void unpack2(ull v, float& lo, float& hi) {
    asm("mov.b64 {%0, %1}, %2;" : "=f"(lo), "=f"(hi) : "l"(v));
}
__device__ __forceinline__ float ex2f(float x) {
    float e; asm("ex2.approx.ftz.f32 %0, %1;" : "=f"(e) : "f"(x));
    return e;
}

// ---------------------------------------------------------------------------
// Shared update math: given the 8 reduced sums p[] and T_old, produce T_new.
// R_delta = V @ U^T (SVD of H) == orthogonal polar factor of H^T, closed form.
// MUST be called with identical inputs everywhere it's used (bit-identical).
// ---------------------------------------------------------------------------
__device__ __forceinline__ void icp_compose(const float p[8],
                                            float cc, float ss, float ttx, float tty,
                                            float& c2, float& s2, float& tx2, float& ty2) {
    const float invN = 1.0f / (float)NN;
    const float csx = p[0] * invN, csy = p[1] * invN;
    const float ctx = p[2] * invN, cty = p[3] * invN;

    const float h00 = p[4] - p[0] * p[2] * invN;
    const float h01 = p[5] - p[0] * p[3] * invN;
    const float h10 = p[6] - p[1] * p[2] * invN;
    const float h11 = p[7] - p[1] * p[3] * invN;

    const float E  = 0.5f * (h00 + h11);
    const float F  = 0.5f * (h00 - h11);
    const float G  = 0.5f * (h01 + h10);
    const float Hh = 0.5f * (h01 - h10);
    const float det = h00 * h11 - h01 * h10;

    float r00, r01, r10, r11;
    if (det >= 0.0f) {           // rotation branch
        float iq = rsqrtf(E * E + Hh * Hh);
        r00 =  E * iq;  r01 = -Hh * iq;
        r10 = Hh * iq;  r11 =  E * iq;
    } else {                      // reflection branch
        float ir = rsqrtf(F * F + G * G);
        r00 =  F * ir;  r01 =  G * ir;
        r10 =  G * ir;  r11 = -F * ir;
    }

    const float ih = rsqrtf(r00 * r00 + r10 * r10);
    const float cD = r00 * ih;
    const float sD = r10 * ih;
    const float tDx = ctx - (r00 * csx + r01 * csy);
    const float tDy = cty - (r10 * csx + r11 * csy);

    c2  = cD * cc - sD * ss;
    s2  = sD * cc + cD * ss;
    tx2 = cD * ttx - sD * tty + tDx;
    ty2 = sD * ttx + cD * tty + tDy;
}

// ---------------------------------------------------------------------------
// Init: paired, log2e-folded target constants + initial transform (buf 0).
// ---------------------------------------------------------------------------
__global__ void icp_init_kernel(const float* __restrict__ target,
                                const float* __restrict__ init_t) {
    int g = blockIdx.x * blockDim.x + threadIdx.x;
    if (g < BB * NPAIR) {
        int b = g >> 10, p = g & (NPAIR - 1);
        float4 f = reinterpret_cast<const float4*>(target)[(size_t)b * NPAIR + p];
        const float L2E = 1.4426950408889634f;
        ulonglong2 uv;
        uv.x = pack2(2.0f * L2E * f.x, 2.0f * L2E * f.z);
        uv.y = pack2(2.0f * L2E * f.y, 2.0f * L2E * f.w);
        g_uv2[b][p] = uv;
        g_w2[b][p]  = pack2(-L2E * (f.x * f.x + f.y * f.y),
                            -L2E * (f.z * f.z + f.w * f.w));
    }
    if (g < BB) {
        float th = init_t[g * 3 + 0];
        g_Tbuf[0][g][0] = cosf(th);
        g_Tbuf[0][g][1] = sinf(th);
        g_Tbuf[0][g][2] = init_t[g * 3 + 1];
        g_Tbuf[0][g][3] = init_t[g * 3 + 2];
    }
}

// ---------------------------------------------------------------------------
// Iter kernel `it` (0..4). grid = BB*CHUNKS = 1024 CTAs, block = 128.
// Head (it>0): redundantly reduce previous g_part + compose T_it from
//   T_{it-1} (read from g_Tbuf[it&1]); chunk0 persists T_it to g_Tbuf[(it+1)&1].
// Head (it==0): T_0 read directly from g_Tbuf[0]; chunk0 copies to g_Tbuf[1].
// Body: MUFU-paced softmax mainloop writing this iteration's g_part.
// ---------------------------------------------------------------------------
__global__ void __launch_bounds__(TPB, 8)
icp_iter_kernel(const float* __restrict__ source, int it) {
    __shared__ ulonglong2 sUV[NPAIR];                     // 16 KB
    __shared__ ull        sW[NPAIR];                      // 8 KB
    __shared__ float4     sRow[MSPLIT - 1][ROWS_PER_CTA]; // 3 KB

    const int b     = blockIdx.x >> 5;
    const int chunk = blockIdx.x & 31;
    const int tid   = threadIdx.x;
    const int lane  = tid & 31;
    const int warp  = tid >> 5;          // == M-segment

    // Stage paired target constants (coalesced 16B/8B loads)
    for (int i = tid; i < NPAIR; i += TPB) {
        sUV[i] = g_uv2[b][i];
        sW[i]  = g_w2[b][i];
    }

    // ---- compute this iteration's transform (redundant per warp) ----
    const int rd = it & 1;
    float c, s, tx, ty;
    {
        const float cc  = g_Tbuf[rd][b][0];
        const float ss  = g_Tbuf[rd][b][1];
        const float ttx = g_Tbuf[rd][b][2];
        const float tty = g_Tbuf[rd][b][3];
        if (it == 0) {
            c = cc; s = ss; tx = ttx; ty = tty;
        } else {
            // lane == chunk index: reduce previous iteration's partials
            float p[8];
            #pragma unroll
            for (int k = 0; k < 8; ++k) p[k] = g_part[b][lane][k];
            #pragma unroll
            for (int off = 16; off; off >>= 1)
                #pragma unroll
                for (int k = 0; k < 8; ++k)
                    p[k] += __shfl_xor_sync(0xFFFFFFFFu, p[k], off);
            icp_compose(p, cc, ss, ttx, tty, c, s, tx, ty);
        }
        // persist T_it for the next kernel (double-buffered: no read/write race)
        if (chunk == 0 && tid == 0) {
            g_Tbuf[rd ^ 1][b][0] = c;
            g_Tbuf[rd ^ 1][b][1] = s;
            g_Tbuf[rd ^ 1][b][2] = tx;
            g_Tbuf[rd ^ 1][b][3] = ty;
        }
    }

    // st = R*source + t for this thread's 2 rows
    float sx[RPT], sy[RPT];
    ull sx2[RPT], sy2[RPT];
    #pragma unroll
    for (int k = 0; k < RPT; ++k) {
        const int row = chunk * ROWS_PER_CTA + lane + 32 * k;
        const float2 sv = reinterpret_cast<const float2*>(source)[(size_t)b * NN + row];
        sx[k] = c * sv.x - s * sv.y + tx;
        sy[k] = s * sv.x + c * sv.y + ty;
        sx2[k] = pack2(sx[k], sx[k]);
        sy2[k] = pack2(sy[k], sy[k]);
    }

    __syncthreads();

    // Packed single-pass softmax-weighted sums: 2 LDS/pair, reused x2 rows.
    ull se2[RPT], au2[RPT], av2[RPT];
    #pragma unroll
    for (int k = 0; k < RPT; ++k) { se2[k] = 0ull; au2[k] = 0ull; av2[k] = 0ull; }

    const int p0 = warp * SEGPAIRS;
    #pragma unroll 4
    for (int p = p0; p < p0 + SEGPAIRS; ++p) {
        const ulonglong2 uv = sUV[p];
        const ull u2 = uv.x;
        const ull v2 = uv.y;
        const ull w2 = sW[p];
        #pragma unroll
        for (int k = 0; k < RPT; ++k) {
            ull y2 = fma2(sx2[k], u2, w2);
            y2 = fma2(sy2[k], v2, y2);
            float y0, y1; unpack2(y2, y0, y1);
            const ull e2 = pack2(ex2f(y0), ex2f(y1));
            se2[k] = add2(se2[k], e2);
            au2[k] = fma2(e2, u2, au2[k]);
            av2[k] = fma2(e2, v2, av2[k]);
        }
    }

    // Horizontal add of the packed halves (fixed order: lo + hi)
    float se[RPT], au[RPT], av[RPT];
    #pragma unroll
    for (int k = 0; k < RPT; ++k) {
        float a0, a1;
        unpack2(se2[k], a0, a1); se[k] = a0 + a1;
        unpack2(au2[k], a0, a1); au[k] = a0 + a1;
        unpack2(av2[k], a0, a1); av[k] = a0 + a1;
    }

    // Publish segment partials (warps 1..3), combine in warp 0 (fixed order)
    if (warp > 0) {
        #pragma unroll
        for (int k = 0; k < RPT; ++k)
            sRow[warp - 1][lane + 32 * k] = make_float4(se[k], au[k], av[k], 0.0f);
    }
    __syncthreads();

    if (warp == 0) {
        float p[8];
        #pragma unroll
        for (int i = 0; i < 8; ++i) p[i] = 0.0f;

        #pragma unroll
        for (int k = 0; k < RPT; ++k) {
            float sek = se[k], auk = au[k], avk = av[k];
            #pragma unroll
            for (int q = 0; q < MSPLIT - 1; ++q) {   // fixed order seg1..3
                const float4 f = sRow[q][lane + 32 * k];
                sek += f.x; auk += f.y; avk += f.z;
            }
            const float KINV = 0.34657359027997264f; // ln(2)/2 (undo folded 2*log2e)
            const float inv = KINV / sek;
            const float tcx = auk * inv;
            const float tcy = avk * inv;
            // fixed-order accumulation over k
            p[0] += sx[k];        p[1] += sy[k];
            p[2] += tcx;          p[3] += tcy;
            p[4] += sx[k] * tcx;  p[5] += sx[k] * tcy;
            p[6] += sy[k] * tcx;  p[7] += sy[k] * tcy;
        }

        // Deterministic warp butterfly
        #pragma unroll
        for (int off = 16; off; off >>= 1)
            #pragma unroll
            for (int i = 0; i < 8; ++i)
                p[i] += __shfl_xor_sync(0xFFFFFFFFu, p[i], off);

        if (lane == 0) {
            #pragma unroll
            for (int i = 0; i < 8; ++i) g_part[b][chunk][i] = p[i];
        }
    }
}

// ---------------------------------------------------------------------------
// Final kernel: reduce last iteration's partials, compose T_5, write output.
// grid = BB x 32 threads. Reads T_4 from g_Tbuf[(ITERS)&1] == g_Tbuf[1].
// ---------------------------------------------------------------------------
__global__ void icp_final_kernel(float* __restrict__ out) {
    const int b = blockIdx.x;
    const int t = threadIdx.x;

    float p[8];
    #pragma unroll
    for (int k = 0; k < 8; ++k) p[k] = g_part[b][t][k];
    #pragma unroll
    for (int off = 16; off; off >>= 1)
        #pragma unroll
        for (int k = 0; k < 8; ++k)
            p[k] += __shfl_xor_sync(0xFFFFFFFFu, p[k], off);

    if (t == 0) {
        const int rd = ITERS & 1;   // buffer holding T_{ITERS-1}
        float c2, s2, tx2, ty2;
        icp_compose(p, g_Tbuf[rd][b][0], g_Tbuf[rd][b][1],
                       g_Tbuf[rd][b][2], g_Tbuf[rd][b][3],
                    c2, s2, tx2, ty2);
        out[b * 3 + 0] = atan2f(s2, c2);
        out[b * 3 + 1] = tx2;
        out[b * 3 + 2] = ty2;
    }
}

// ---------------------------------------------------------------------------
extern "C" void kernel_launch(void* const* d_in, const int* in_sizes, int n_in,
                              void* d_out, int out_size) {
    const float* source = (const float*)d_in[0];   // (32, 2048, 2)
    const float* target = (const float*)d_in[1];   // (32, 2048, 2)
    const float* init_t = (const float*)d_in[2];   // (32, 3)
    float* out = (float*)d_out;                    // (32, 3)

    icp_init_kernel<<<(BB * NPAIR + 255) / 256, 256>>>(target, init_t);
    for (int it = 0; it < ITERS; ++it)
        icp_iter_kernel<<<BB * CHUNKS, TPB>>>(source, it);
    icp_final_kernel<<<BB, 32>>>(out);
}